// round 1
// baseline (speedup 1.0000x reference)
#include <cuda_runtime.h>
#include <cuda_bf16.h>
#include <cstdint>

// Problem constants
#define TT    2048
#define BB    32
#define HHID  512
#define KK    1024          // concat input dim [x|h] or [h1|h2]
#define KPAD  1032          // padded K stride in SMEM (conflict-free)
#define NPL   64            // CTAs per layer
#define NCTA  128           // total persistent CTAs
#define BH    (BB*HHID)     // 16384 elements per timestep slice

// ---------------- device global scratch (static, no runtime alloc) ----------
__device__ __nv_bfloat16 g_X[(size_t)TT * BH];                 // gathered embeddings, [t][b][k] bf16
__device__ __nv_bfloat16 g_H[2][(size_t)(TT + 1) * BH];        // h per layer per step, [t][b][u]
__device__ __nv_bfloat16 g_W[(size_t)NCTA * 32 * KK];          // reorganized weights per CTA slice
__device__ float         g_bias[NCTA * 32];                    // combined biases per CTA slice
__device__ int           g_cnt[2 * (TT + 1)];                  // completion counters [layer][t]

// ---------------- helpers ---------------------------------------------------
__device__ __forceinline__ void mma16816(float* c,
                                         uint32_t a0, uint32_t a1, uint32_t a2, uint32_t a3,
                                         uint32_t b0, uint32_t b1) {
    asm volatile(
        "mma.sync.aligned.m16n8k16.row.col.f32.bf16.bf16.f32 "
        "{%0,%1,%2,%3},{%4,%5,%6,%7},{%8,%9},{%0,%1,%2,%3};\n"
        : "+f"(c[0]), "+f"(c[1]), "+f"(c[2]), "+f"(c[3])
        : "r"(a0), "r"(a1), "r"(a2), "r"(a3), "r"(b0), "r"(b1));
}

__device__ __forceinline__ float sigmoidf_(float x) {
    return 1.0f / (1.0f + __expf(-x));
}

// ---------------- prep: reorganize weights to per-CTA bf16 slices -----------
// CTA 'cta' (L = cta/64, s = cta%64) owns hidden units u in [s*8, s*8+8).
// Its 32 rows r = g*8+j map to gate column col = g*512 + s*8 + j.
// K layout: k<512 -> W_ih[col][k] ; k>=512 -> W_hh[col][k-512].
__global__ void prep_w_kernel(const float* __restrict__ w_ih,
                              const float* __restrict__ w_hh,
                              const float* __restrict__ b_ih,
                              const float* __restrict__ b_hh) {
    int idx = blockIdx.x * blockDim.x + threadIdx.x;   // 128*32*1024 = 4194304
    if (idx >= NCTA * 32 * KK) return;
    int k   = idx & 1023;
    int r   = (idx >> 10) & 31;
    int cta = idx >> 15;
    int L = cta >> 6, s = cta & 63;
    int g = r >> 3,  j = r & 7;
    int col = g * 512 + s * 8 + j;
    size_t base = ((size_t)L * 2048 + col) * 512;
    float w = (k < 512) ? w_ih[base + k] : w_hh[base + (k - 512)];
    g_W[idx] = __float2bfloat16(w);
    if (k == 0) g_bias[cta * 32 + r] = b_ih[L * 2048 + col] + b_hh[L * 2048 + col];
}

// ---------------- prep: embedding gather to bf16 [t][b][k] ------------------
__global__ void gather_x_kernel(const int* __restrict__ tokens,
                                const float* __restrict__ emb) {
    int idx = blockIdx.x * blockDim.x + threadIdx.x;   // groups of 8 elems: 2048*32*64
    if (idx >= TT * BB * 64) return;
    int k8 = idx & 63;
    int b  = (idx >> 6) & 31;
    int t  = idx >> 11;
    int tok = tokens[b * TT + t];
    const float* e = emb + (size_t)tok * 512 + k8 * 8;
    __nv_bfloat16 v[8];
#pragma unroll
    for (int i = 0; i < 8; ++i) v[i] = __float2bfloat16(e[i]);
    *(uint4*)(g_X + ((size_t)t * BB + b) * 512 + k8 * 8) = *(uint4*)v;
}

// ---------------- prep: init state (h[.,0]=0, counters) ---------------------
__global__ void init_kernel() {
    int idx = blockIdx.x * blockDim.x + threadIdx.x;   // 64*256 = 16384
    if (idx < BH) {
        __nv_bfloat16 z = __float2bfloat16(0.0f);
        g_H[0][idx] = z;
        g_H[1][idx] = z;
    }
    if (idx < 2 * (TT + 1)) {
        g_cnt[idx] = (idx == 0 || idx == (TT + 1)) ? NPL : 0;  // cnt[L][0] pre-satisfied
    }
}

// ---------------- the persistent LSTM kernel --------------------------------
// grid = 128 CTAs (64 layer0 + 64 layer1), 256 threads, ~150KB dyn smem, 1 CTA/SM.
// SMEM: W[32][KPAD] bf16 | Act[32][KPAD] bf16 | Psum[4][32][33] f32 | Bias[32] | C[8][33]
#define SMEM_BYTES (2*(32*KPAD*2) + 4*32*33*4 + 32*4 + 8*33*4)

__global__ void __launch_bounds__(256, 1) lstm_kernel() {
    extern __shared__ unsigned char smem_raw[];
    __nv_bfloat16* Wsh  = (__nv_bfloat16*)smem_raw;
    __nv_bfloat16* Ash  = Wsh + 32 * KPAD;
    float*         Psum = (float*)(Ash + 32 * KPAD);
    float*         Bias = Psum + 4 * 32 * 33;
    float*         Csh  = Bias + 32;

    const int tid = threadIdx.x;
    const int cta = blockIdx.x;
    const int L = cta >> 6;       // layer
    const int s = cta & 63;       // slice -> hidden units [s*8, s*8+8)

    // --- load resident weights/bias, zero cell state ---
    const __nv_bfloat16* wsrc = g_W + (size_t)cta * 32 * KK;
    for (int i = tid; i < 4096; i += 256) {       // 4096 x 16B = 64KB
        int r = i >> 7, c = (i & 127) << 3;
        *(uint4*)(Wsh + r * KPAD + c) = __ldcg((const uint4*)(wsrc + (size_t)i * 8));
    }
    for (int i = tid; i < 32; i += 256) Bias[i] = g_bias[cta * 32 + i];
    for (int i = tid; i < 8 * 33; i += 256) Csh[i] = 0.0f;
    __syncthreads();

    const int warp = tid >> 5, lane = tid & 31;
    const int mh = warp >> 2, kq = warp & 3;       // (m-half, k-quarter)
    const int gid = lane >> 2, t4 = lane & 3;
    const int rlo = mh * 16 + gid;
    volatile int* vcnt = (volatile int*)g_cnt;

    const int bact = tid >> 3, jact = tid & 7;     // activation mapping: tid = b*8 + j

    for (int t = 1; t <= TT; ++t) {
        // ---- wait for producers ----
        if (tid == 0) {
            if (L == 0) {
                while (vcnt[t - 1] < NPL) __nanosleep(64);               // cnt[0][t-1]
            } else {
                while (vcnt[t] < NPL) __nanosleep(64);                   // cnt[0][t]
                while (vcnt[(TT + 1) + (t - 1)] < NPL) __nanosleep(64);  // cnt[1][t-1]
            }
            __threadfence();
        }
        __syncthreads();

        // ---- stage activations [x|h] or [h1|h2] into SMEM (32 x 1024 bf16) ----
        const __nv_bfloat16* src0 = (L == 0) ? (g_X + (size_t)(t - 1) * BH)
                                             : (g_H[0] + (size_t)t * BH);
        const __nv_bfloat16* src1 = g_H[L] + (size_t)(t - 1) * BH;
        for (int i = tid; i < 2048; i += 256) {
            int b = i >> 6, c = (i & 63) << 3;
            *(uint4*)(Ash + b * KPAD + c) = __ldcg((const uint4*)(src0 + b * 512 + c));
        }
        for (int i = tid; i < 2048; i += 256) {
            int b = i >> 6, c = (i & 63) << 3;
            *(uint4*)(Ash + b * KPAD + 512 + c) = __ldcg((const uint4*)(src1 + b * 512 + c));
        }
        __syncthreads();

        // ---- GEMM: gates[32 rows][32 batch] = W[32][1024] x Act^T ----
        float acc[4][4];
#pragma unroll
        for (int n = 0; n < 4; ++n)
#pragma unroll
            for (int q = 0; q < 4; ++q) acc[n][q] = 0.0f;

#pragma unroll
        for (int kc = 0; kc < 16; ++kc) {
            const int k0 = kq * 256 + kc * 16;
            uint32_t a0 = *(const uint32_t*)(Wsh + rlo * KPAD + k0 + t4 * 2);
            uint32_t a1 = *(const uint32_t*)(Wsh + (rlo + 8) * KPAD + k0 + t4 * 2);
            uint32_t a2 = *(const uint32_t*)(Wsh + rlo * KPAD + k0 + 8 + t4 * 2);
            uint32_t a3 = *(const uint32_t*)(Wsh + (rlo + 8) * KPAD + k0 + 8 + t4 * 2);
#pragma unroll
            for (int nt = 0; nt < 4; ++nt) {
                const int col = nt * 8 + gid;
                uint32_t b0 = *(const uint32_t*)(Ash + col * KPAD + k0 + t4 * 2);
                uint32_t b1 = *(const uint32_t*)(Ash + col * KPAD + k0 + 8 + t4 * 2);
                mma16816(acc[nt], a0, a1, a2, a3, b0, b1);
            }
        }

        // ---- write k-partials ----
#pragma unroll
        for (int nt = 0; nt < 4; ++nt) {
            int r = mh * 16 + gid;
            int c = nt * 8 + t4 * 2;
            Psum[(kq * 32 + r)     * 33 + c]     = acc[nt][0];
            Psum[(kq * 32 + r)     * 33 + c + 1] = acc[nt][1];
            Psum[(kq * 32 + r + 8) * 33 + c]     = acc[nt][2];
            Psum[(kq * 32 + r + 8) * 33 + c + 1] = acc[nt][3];
        }
        __syncthreads();

        // ---- reduce + LSTM cell update: one thread per (unit j, batch b) ----
        {
            float gv[4];
#pragma unroll
            for (int g = 0; g < 4; ++g) {
                int r = g * 8 + jact;
                float v = Bias[r];
#pragma unroll
                for (int q = 0; q < 4; ++q) v += Psum[(q * 32 + r) * 33 + bact];
                gv[g] = v;
            }
            float ig = sigmoidf_(gv[0]);
            float fg = sigmoidf_(gv[1]);
            float gg = tanhf(gv[2]);
            float og = sigmoidf_(gv[3]);
            float c_old = Csh[jact * 33 + bact];
            float c_new = fg * c_old + ig * gg;
            float h_new = og * tanhf(c_new);
            Csh[jact * 33 + bact] = c_new;
            g_H[L][(size_t)t * BH + bact * 512 + s * 8 + jact] = __float2bfloat16(h_new);
        }
        __syncthreads();

        // ---- publish ----
        if (tid == 0) {
            __threadfence();
            atomicAdd(&g_cnt[L * (TT + 1) + t], 1);
        }
    }
}

// ---------------- final FC + sigmoid ----------------------------------------
__global__ void fc_kernel(const float* __restrict__ fc_w,
                          const float* __restrict__ fc_b,
                          float* __restrict__ out) {
    int tid = threadIdx.x;            // 64 threads: b = tid/2, o = tid%2
    if (tid >= 64) return;
    int b = tid >> 1, o = tid & 1;
    const __nv_bfloat16* h = g_H[1] + (size_t)TT * BH + b * 512;
    float sum = fc_b[o];
    for (int u = 0; u < 512; ++u)
        sum += __bfloat162float(h[u]) * fc_w[o * 512 + u];
    out[b * 2 + o] = sigmoidf_(sum);
}

// ---------------- launch ------------------------------------------------------
extern "C" void kernel_launch(void* const* d_in, const int* in_sizes, int n_in,
                              void* d_out, int out_size) {
    const int*   tokens = (const int*)d_in[0];
    const float* emb    = (const float*)d_in[1];
    const float* w_ih   = (const float*)d_in[2];
    const float* w_hh   = (const float*)d_in[3];
    const float* b_ih   = (const float*)d_in[4];
    const float* b_hh   = (const float*)d_in[5];
    const float* fc_w   = (const float*)d_in[6];
    const float* fc_b   = (const float*)d_in[7];
    float* out = (float*)d_out;

    cudaFuncSetAttribute(lstm_kernel, cudaFuncAttributeMaxDynamicSharedMemorySize, SMEM_BYTES);

    prep_w_kernel<<<16384, 256>>>(w_ih, w_hh, b_ih, b_hh);
    gather_x_kernel<<<16384, 256>>>(tokens, emb);
    init_kernel<<<64, 256>>>();
    lstm_kernel<<<NCTA, 256, SMEM_BYTES>>>();
    fc_kernel<<<1, 64>>>(fc_w, fc_b, out);
}

// round 2
// speedup vs baseline: 1.1024x; 1.1024x over previous
#include <cuda_runtime.h>
#include <cuda_bf16.h>
#include <cstdint>

// Problem constants
#define TT    2048
#define BB    32
#define HHID  512
#define KK    1024          // concat input dim [x|h] or [h1|h2]
#define KPAD  1032          // padded K stride in SMEM (conflict-free)
#define NPL   64            // CTAs per layer
#define NCTA  128           // total persistent CTAs
#define BH    (BB*HHID)     // 16384 elements per timestep slice

// ---------------- device global scratch -------------------------------------
__device__ __nv_bfloat16 g_X[(size_t)TT * BH];                 // gathered embeddings
__device__ __nv_bfloat16 g_H[2][(size_t)(TT + 1) * BH];        // h per layer per step
__device__ __nv_bfloat16 g_W[(size_t)NCTA * 32 * KK];          // per-CTA weight slices
__device__ float         g_bias[NCTA * 32];
__device__ int           g_cnt[2 * (TT + 1)];                  // [layer][t] counters

// ---------------- helpers ---------------------------------------------------
__device__ __forceinline__ void mma16816(float* c, const uint32_t* a,
                                         uint32_t b0, uint32_t b1) {
    asm volatile(
        "mma.sync.aligned.m16n8k16.row.col.f32.bf16.bf16.f32 "
        "{%0,%1,%2,%3},{%4,%5,%6,%7},{%8,%9},{%0,%1,%2,%3};\n"
        : "+f"(c[0]), "+f"(c[1]), "+f"(c[2]), "+f"(c[3])
        : "r"(a[0]), "r"(a[1]), "r"(a[2]), "r"(a[3]), "r"(b0), "r"(b1));
}

__device__ __forceinline__ float sigmoidf_(float x) {
    return 1.0f / (1.0f + __expf(-x));
}

__device__ __forceinline__ int ld_acq(const int* p) {
    int v;
    asm volatile("ld.acquire.gpu.global.s32 %0, [%1];" : "=r"(v) : "l"(p) : "memory");
    return v;
}
__device__ __forceinline__ void red_rel(int* p) {
    asm volatile("red.release.gpu.global.add.s32 [%0], 1;" :: "l"(p) : "memory");
}
__device__ __forceinline__ void wait_ge(const int* p, int target) {
    if (ld_acq(p) >= target) return;
    while (ld_acq(p) < target) __nanosleep(32);
}
__device__ __forceinline__ void cp16(uint32_t dst_smem, const void* src) {
    asm volatile("cp.async.cg.shared.global [%0], [%1], 16;\n" :: "r"(dst_smem), "l"(src));
}

// ---------------- prep: reorganize weights to per-CTA bf16 slices -----------
__global__ void prep_w_kernel(const float* __restrict__ w_ih,
                              const float* __restrict__ w_hh,
                              const float* __restrict__ b_ih,
                              const float* __restrict__ b_hh) {
    int idx = blockIdx.x * blockDim.x + threadIdx.x;
    if (idx >= NCTA * 32 * KK) return;
    int k   = idx & 1023;
    int r   = (idx >> 10) & 31;
    int cta = idx >> 15;
    int L = cta >> 6, s = cta & 63;
    int g = r >> 3,  j = r & 7;
    int col = g * 512 + s * 8 + j;
    size_t base = ((size_t)L * 2048 + col) * 512;
    float w = (k < 512) ? w_ih[base + k] : w_hh[base + (k - 512)];
    g_W[idx] = __float2bfloat16(w);
    if (k == 0) g_bias[cta * 32 + r] = b_ih[L * 2048 + col] + b_hh[L * 2048 + col];
}

// ---------------- prep: embedding gather to bf16 [t][b][k] ------------------
__global__ void gather_x_kernel(const int* __restrict__ tokens,
                                const float* __restrict__ emb) {
    int idx = blockIdx.x * blockDim.x + threadIdx.x;
    if (idx >= TT * BB * 64) return;
    int k8 = idx & 63;
    int b  = (idx >> 6) & 31;
    int t  = idx >> 11;
    int tok = tokens[b * TT + t];
    const float* e = emb + (size_t)tok * 512 + k8 * 8;
    __nv_bfloat16 v[8];
#pragma unroll
    for (int i = 0; i < 8; ++i) v[i] = __float2bfloat16(e[i]);
    *(uint4*)(g_X + ((size_t)t * BB + b) * 512 + k8 * 8) = *(uint4*)v;
}

// ---------------- prep: init state ------------------------------------------
__global__ void init_kernel() {
    int idx = blockIdx.x * blockDim.x + threadIdx.x;
    if (idx < BH) {
        __nv_bfloat16 z = __float2bfloat16(0.0f);
        g_H[0][idx] = z;
        g_H[1][idx] = z;
    }
    if (idx < 2 * (TT + 1)) {
        g_cnt[idx] = (idx == 0 || idx == (TT + 1)) ? NPL : 0;
    }
}

// ---------------- the persistent LSTM kernel --------------------------------
// 128 CTAs (64/layer), 256 threads. Weights live in REGISTERS (64 u32/lane).
// Warps: ks = warp (0..7) -> k-slices [ks*64, ks*64+64) in each of x/h halves.
// Each warp: M=32 (all rows), N=32 (all batch), K=128.
// SMEM: Act[32][KPAD] bf16 | Psum[8*32][33] f32
#define SMEM_ACT_BYTES (32 * KPAD * 2)
#define SMEM_BYTES     (SMEM_ACT_BYTES + 8 * 32 * 33 * 4)

__global__ void __launch_bounds__(256, 1) lstm_kernel() {
    extern __shared__ unsigned char smem_raw[];
    __nv_bfloat16* Ash  = (__nv_bfloat16*)smem_raw;
    float*         Psum = (float*)(smem_raw + SMEM_ACT_BYTES);
    uint32_t ash_s = (uint32_t)__cvta_generic_to_shared(Ash);

    const int tid = threadIdx.x;
    const int cta = blockIdx.x;
    const int L = cta >> 6;
    const int s = cta & 63;

    const int ks   = tid >> 5;          // warp = k-slice
    const int lane = tid & 31;
    const int gid  = lane >> 2;
    const int t4   = lane & 3;

    // ---- load weight fragments into registers (once) ----
    const __nv_bfloat16* wsrc = g_W + (size_t)cta * 32 * KK;
    uint32_t areg[2][4][2][4];          // [half][kc][mb][frag]
#pragma unroll
    for (int half = 0; half < 2; ++half)
#pragma unroll
        for (int kc = 0; kc < 4; ++kc) {
            int k0 = half * 512 + ks * 64 + kc * 16 + t4 * 2;
#pragma unroll
            for (int mb = 0; mb < 2; ++mb) {
                int r = mb * 16 + gid;
                areg[half][kc][mb][0] = *(const uint32_t*)(wsrc + r * KK + k0);
                areg[half][kc][mb][1] = *(const uint32_t*)(wsrc + (r + 8) * KK + k0);
                areg[half][kc][mb][2] = *(const uint32_t*)(wsrc + r * KK + k0 + 8);
                areg[half][kc][mb][3] = *(const uint32_t*)(wsrc + (r + 8) * KK + k0 + 8);
            }
        }

    // ---- bias + cell state in registers (update thread mapping) ----
    const int bact = tid >> 3, jact = tid & 7;      // tid = b*8 + j
    float bias_r[4];
#pragma unroll
    for (int g = 0; g < 4; ++g) bias_r[g] = g_bias[cta * 32 + g * 8 + jact];
    float c_reg = 0.0f;

    int* cnt_own  = &g_cnt[L * (TT + 1)];
    int* cnt_l0   = &g_cnt[0];

    for (int t = 1; t <= TT; ++t) {
        float acc[2][4][4];
#pragma unroll
        for (int mb = 0; mb < 2; ++mb)
#pragma unroll
            for (int nt = 0; nt < 4; ++nt)
#pragma unroll
                for (int i = 0; i < 4; ++i) acc[mb][nt][i] = 0.0f;

        // ================= phase A: x-half (k < 512) =================
        if (L == 1) {
            if (tid == 0) wait_ge(&cnt_l0[t], NPL);   // need h0[t]
            __syncthreads();
        }
        {
            const __nv_bfloat16* srcx = (L == 0) ? (g_X + (size_t)(t - 1) * BH)
                                                 : (g_H[0] + (size_t)t * BH);
#pragma unroll
            for (int i = 0; i < 8; ++i) {
                int idx = tid + i * 256;
                int b = idx >> 6, c = (idx & 63) << 3;
                cp16(ash_s + (b * KPAD + c) * 2, srcx + b * 512 + c);
            }
            asm volatile("cp.async.commit_group;\n" ::: "memory");
            asm volatile("cp.async.wait_group 0;\n" ::: "memory");
        }
        __syncthreads();

#pragma unroll
        for (int kc = 0; kc < 4; ++kc) {
            int k0 = ks * 64 + kc * 16 + t4 * 2;
#pragma unroll
            for (int nt = 0; nt < 4; ++nt) {
                const __nv_bfloat16* bp = Ash + (nt * 8 + gid) * KPAD + k0;
                uint32_t b0 = *(const uint32_t*)bp;
                uint32_t b1 = *(const uint32_t*)(bp + 8);
                mma16816(acc[0][nt], areg[0][kc][0], b0, b1);
                mma16816(acc[1][nt], areg[0][kc][1], b0, b1);
            }
        }

        // ================= phase B: h-half (k >= 512) =================
        if (tid == 0) wait_ge(&cnt_own[t - 1], NPL);
        __syncthreads();
        {
            const __nv_bfloat16* srch = g_H[L] + (size_t)(t - 1) * BH;
#pragma unroll
            for (int i = 0; i < 8; ++i) {
                int idx = tid + i * 256;
                int b = idx >> 6, c = (idx & 63) << 3;
                cp16(ash_s + (b * KPAD + 512 + c) * 2, srch + b * 512 + c);
            }
            asm volatile("cp.async.commit_group;\n" ::: "memory");
            asm volatile("cp.async.wait_group 0;\n" ::: "memory");
        }
        __syncthreads();

#pragma unroll
        for (int kc = 0; kc < 4; ++kc) {
            int k0 = 512 + ks * 64 + kc * 16 + t4 * 2;
#pragma unroll
            for (int nt = 0; nt < 4; ++nt) {
                const __nv_bfloat16* bp = Ash + (nt * 8 + gid) * KPAD + k0;
                uint32_t b0 = *(const uint32_t*)bp;
                uint32_t b1 = *(const uint32_t*)(bp + 8);
                mma16816(acc[0][nt], areg[1][kc][0], b0, b1);
                mma16816(acc[1][nt], areg[1][kc][1], b0, b1);
            }
        }

        // ---- write k-partials ----
#pragma unroll
        for (int mb = 0; mb < 2; ++mb)
#pragma unroll
            for (int nt = 0; nt < 4; ++nt) {
                int r = ks * 32 + mb * 16 + gid;
                int c = nt * 8 + t4 * 2;
                Psum[r * 33 + c]           = acc[mb][nt][0];
                Psum[r * 33 + c + 1]       = acc[mb][nt][1];
                Psum[(r + 8) * 33 + c]     = acc[mb][nt][2];
                Psum[(r + 8) * 33 + c + 1] = acc[mb][nt][3];
            }
        __syncthreads();

        // ---- reduce + cell update: thread (b = tid>>3, j = tid&7) ----
        {
            float gv[4];
#pragma unroll
            for (int g = 0; g < 4; ++g) {
                int row = g * 8 + jact;
                float v = bias_r[g];
#pragma unroll
                for (int w = 0; w < 8; ++w) v += Psum[(w * 32 + row) * 33 + bact];
                gv[g] = v;
            }
            float ig = sigmoidf_(gv[0]);
            float fg = sigmoidf_(gv[1]);
            float gg = tanhf(gv[2]);
            float og = sigmoidf_(gv[3]);
            c_reg = fg * c_reg + ig * gg;
            float h_new = og * tanhf(c_reg);
            g_H[L][(size_t)t * BH + bact * 512 + s * 8 + jact] = __float2bfloat16(h_new);
        }
        __syncthreads();

        // ---- publish ----
        if (tid == 0) red_rel(&cnt_own[t]);
    }
}

// ---------------- final FC + sigmoid ----------------------------------------
__global__ void fc_kernel(const float* __restrict__ fc_w,
                          const float* __restrict__ fc_b,
                          float* __restrict__ out) {
    __shared__ float part[512];
    int tid = threadIdx.x;                 // 512 threads: (b, o, p8)
    int p = tid & 7, o = (tid >> 3) & 1, b = tid >> 4;
    const __nv_bfloat16* h = g_H[1] + (size_t)TT * BH + b * 512 + p * 64;
    const float* w = fc_w + o * 512 + p * 64;
    float sum = 0.0f;
#pragma unroll
    for (int u = 0; u < 64; ++u) sum += __bfloat162float(h[u]) * w[u];
    part[tid] = sum;
    __syncthreads();
    if (p == 0) {
        float v = fc_b[o];
#pragma unroll
        for (int q = 0; q < 8; ++q) v += part[tid + q];
        out[b * 2 + o] = sigmoidf_(v);
    }
}

// ---------------- launch -----------------------------------------------------
extern "C" void kernel_launch(void* const* d_in, const int* in_sizes, int n_in,
                              void* d_out, int out_size) {
    const int*   tokens = (const int*)d_in[0];
    const float* emb    = (const float*)d_in[1];
    const float* w_ih   = (const float*)d_in[2];
    const float* w_hh   = (const float*)d_in[3];
    const float* b_ih   = (const float*)d_in[4];
    const float* b_hh   = (const float*)d_in[5];
    const float* fc_w   = (const float*)d_in[6];
    const float* fc_b   = (const float*)d_in[7];
    float* out = (float*)d_out;

    cudaFuncSetAttribute(lstm_kernel, cudaFuncAttributeMaxDynamicSharedMemorySize, SMEM_BYTES);

    prep_w_kernel<<<16384, 256>>>(w_ih, w_hh, b_ih, b_hh);
    gather_x_kernel<<<16384, 256>>>(tokens, emb);
    init_kernel<<<64, 256>>>();
    lstm_kernel<<<NCTA, 256, SMEM_BYTES>>>();
    fc_kernel<<<1, 512>>>(fc_w, fc_b, out);
}

// round 3
// speedup vs baseline: 1.3594x; 1.2331x over previous
#include <cuda_runtime.h>
#include <cuda_bf16.h>
#include <cstdint>

// Problem constants
#define TT    2048
#define BB    32
#define HHID  512
#define KK    1024          // concat input dim [x|h] or [h1|h2]
#define KPAD  1032          // padded K stride in SMEM (conflict-free)
#define NPL   64            // CTAs per layer
#define NCTA  128           // total persistent CTAs
#define BH    (BB*HHID)     // 16384 elements per timestep slice

// ---------------- device global scratch -------------------------------------
__device__ __nv_bfloat16 g_X[(size_t)TT * BH];                 // gathered embeddings
__device__ __nv_bfloat16 g_H[2][(size_t)(TT + 1) * BH];        // h per layer per step
__device__ __nv_bfloat16 g_W[(size_t)NCTA * 32 * KK];          // per-CTA weight slices
__device__ float         g_bias[NCTA * 32];
__device__ int           g_cnt[2 * (TT + 1)];                  // [layer][t] counters

// ---------------- helpers ---------------------------------------------------
__device__ __forceinline__ void mma16816(float* c, const uint32_t* a,
                                         uint32_t b0, uint32_t b1) {
    asm volatile(
        "mma.sync.aligned.m16n8k16.row.col.f32.bf16.bf16.f32 "
        "{%0,%1,%2,%3},{%4,%5,%6,%7},{%8,%9},{%0,%1,%2,%3};\n"
        : "+f"(c[0]), "+f"(c[1]), "+f"(c[2]), "+f"(c[3])
        : "r"(a[0]), "r"(a[1]), "r"(a[2]), "r"(a[3]), "r"(b0), "r"(b1));
}

__device__ __forceinline__ float sigmoidf_(float x) {
    return 1.0f / (1.0f + __expf(-x));
}

__device__ __forceinline__ int ld_acq(const int* p) {
    int v;
    asm volatile("ld.acquire.gpu.global.s32 %0, [%1];" : "=r"(v) : "l"(p) : "memory");
    return v;
}
__device__ __forceinline__ void red_rel(int* p) {
    asm volatile("red.release.gpu.global.add.s32 [%0], 1;" :: "l"(p) : "memory");
}
// warp-collective wait: lane0 polls, broadcast via shfl
__device__ __forceinline__ void wait_warp(const int* p, int target, int lane) {
    int v = 0;
    if (lane == 0) v = ld_acq(p);
    v = __shfl_sync(0xffffffffu, v, 0);
    while (v < target) {
        __nanosleep(32);
        if (lane == 0) v = ld_acq(p);
        v = __shfl_sync(0xffffffffu, v, 0);
    }
}
__device__ __forceinline__ void cp16(uint32_t dst_smem, const void* src) {
    asm volatile("cp.async.cg.shared.global [%0], [%1], 16;\n" :: "r"(dst_smem), "l"(src));
}
__device__ __forceinline__ void cp_commit() {
    asm volatile("cp.async.commit_group;\n" ::: "memory");
}
template<int N>
__device__ __forceinline__ void cp_wait() {
    asm volatile("cp.async.wait_group %0;\n" :: "n"(N) : "memory");
}

// ---------------- prep: reorganize weights to per-CTA bf16 slices -----------
__global__ void prep_w_kernel(const float* __restrict__ w_ih,
                              const float* __restrict__ w_hh,
                              const float* __restrict__ b_ih,
                              const float* __restrict__ b_hh) {
    int idx = blockIdx.x * blockDim.x + threadIdx.x;
    if (idx >= NCTA * 32 * KK) return;
    int k   = idx & 1023;
    int r   = (idx >> 10) & 31;
    int cta = idx >> 15;
    int L = cta >> 6, s = cta & 63;
    int g = r >> 3,  j = r & 7;
    int col = g * 512 + s * 8 + j;
    size_t base = ((size_t)L * 2048 + col) * 512;
    float w = (k < 512) ? w_ih[base + k] : w_hh[base + (k - 512)];
    g_W[idx] = __float2bfloat16(w);
    if (k == 0) g_bias[cta * 32 + r] = b_ih[L * 2048 + col] + b_hh[L * 2048 + col];
}

// ---------------- prep: embedding gather to bf16 [t][b][k] ------------------
__global__ void gather_x_kernel(const int* __restrict__ tokens,
                                const float* __restrict__ emb) {
    int idx = blockIdx.x * blockDim.x + threadIdx.x;
    if (idx >= TT * BB * 64) return;
    int k8 = idx & 63;
    int b  = (idx >> 6) & 31;
    int t  = idx >> 11;
    int tok = tokens[b * TT + t];
    const float* e = emb + (size_t)tok * 512 + k8 * 8;
    __nv_bfloat16 v[8];
#pragma unroll
    for (int i = 0; i < 8; ++i) v[i] = __float2bfloat16(e[i]);
    *(uint4*)(g_X + ((size_t)t * BB + b) * 512 + k8 * 8) = *(uint4*)v;
}

// ---------------- prep: init state ------------------------------------------
__global__ void init_kernel() {
    int idx = blockIdx.x * blockDim.x + threadIdx.x;
    if (idx < BH) {
        __nv_bfloat16 z = __float2bfloat16(0.0f);
        g_H[0][idx] = z;
        g_H[1][idx] = z;
    }
    if (idx < 2 * (TT + 1)) {
        g_cnt[idx] = (idx == 0 || idx == (TT + 1)) ? NPL : 0;
    }
}

// ---------------- the persistent LSTM kernel --------------------------------
// 128 CTAs (64/layer), 256 threads. Weights in registers.
// Warp ks owns k-columns [ks*64, ks*64+64) of each half; loads ONLY its own
// columns (per-warp polls + cp.async, no CTA barrier in the load path).
// x-half (cols 0..511) is prefetched one step ahead.
#define SMEM_ACT_BYTES (32 * KPAD * 2)
#define SMEM_BYTES     (SMEM_ACT_BYTES + 8 * 32 * 33 * 4)

__global__ void __launch_bounds__(256, 1) lstm_kernel() {
    extern __shared__ unsigned char smem_raw[];
    __nv_bfloat16* Ash  = (__nv_bfloat16*)smem_raw;
    float*         Psum = (float*)(smem_raw + SMEM_ACT_BYTES);
    uint32_t ash_s = (uint32_t)__cvta_generic_to_shared(Ash);

    const int tid = threadIdx.x;
    const int cta = blockIdx.x;
    const int L = cta >> 6;
    const int s = cta & 63;

    const int ks   = tid >> 5;          // warp = k-slice
    const int lane = tid & 31;
    const int gid  = lane >> 2;
    const int t4   = lane & 3;

    // ---- load weight fragments into registers (once) ----
    const __nv_bfloat16* wsrc = g_W + (size_t)cta * 32 * KK;
    uint32_t areg[2][4][2][4];          // [half][kc][mb][frag]
#pragma unroll
    for (int half = 0; half < 2; ++half)
#pragma unroll
        for (int kc = 0; kc < 4; ++kc) {
            int k0 = half * 512 + ks * 64 + kc * 16 + t4 * 2;
#pragma unroll
            for (int mb = 0; mb < 2; ++mb) {
                int r = mb * 16 + gid;
                areg[half][kc][mb][0] = *(const uint32_t*)(wsrc + r * KK + k0);
                areg[half][kc][mb][1] = *(const uint32_t*)(wsrc + (r + 8) * KK + k0);
                areg[half][kc][mb][2] = *(const uint32_t*)(wsrc + r * KK + k0 + 8);
                areg[half][kc][mb][3] = *(const uint32_t*)(wsrc + (r + 8) * KK + k0 + 8);
            }
        }

    // ---- bias + cell state in registers ----
    const int bact = tid >> 3, jact = tid & 7;      // tid = b*8 + j
    float bias_r[4];
#pragma unroll
    for (int g = 0; g < 4; ++g) bias_r[g] = g_bias[cta * 32 + g * 8 + jact];
    float c_reg = 0.0f;

    int* cnt_own = &g_cnt[L * (TT + 1)];
    int* cnt_l0  = &g_cnt[0];

    // per-warp cp.async lane mapping: 8 chunks of 16B per row-group
    const int c8   = lane & 7;          // chunk within 64-col slice
    const int brow = lane >> 3;         // row group base (4 rows/iter)
    const int kcol = ks * 64 + c8 * 8;  // k-column of this lane's chunks
    const int xdst = (brow * KPAD + kcol);            // element offsets
    const int hdst = (brow * KPAD + 512 + kcol);

    // ---- prologue: prefetch x(1) ----
    if (L == 1) wait_warp(&cnt_l0[1], NPL, lane);
    {
        const __nv_bfloat16* srcx = (L == 0) ? g_X : (g_H[0] + (size_t)BH);
#pragma unroll
        for (int r = 0; r < 8; ++r)
            cp16(ash_s + (xdst + r * 4 * KPAD) * 2, srcx + (brow + r * 4) * 512 + kcol);
        cp_commit();
    }

    for (int t = 1; t <= TT; ++t) {
        float acc[2][4][4];
#pragma unroll
        for (int mb = 0; mb < 2; ++mb)
#pragma unroll
            for (int nt = 0; nt < 4; ++nt)
#pragma unroll
                for (int i = 0; i < 4; ++i) acc[mb][nt][i] = 0.0f;

        // ---- x(t) ready (prefetched) -> x-half MMA (overlaps peers' publish) ----
        cp_wait<0>();
        __syncwarp();
#pragma unroll
        for (int kc = 0; kc < 4; ++kc) {
            int k0 = ks * 64 + kc * 16 + t4 * 2;
#pragma unroll
            for (int nt = 0; nt < 4; ++nt) {
                const __nv_bfloat16* bp = Ash + (nt * 8 + gid) * KPAD + k0;
                uint32_t b0 = *(const uint32_t*)bp;
                uint32_t b1 = *(const uint32_t*)(bp + 8);
                mma16816(acc[0][nt], areg[0][kc][0], b0, b1);
                mma16816(acc[1][nt], areg[0][kc][1], b0, b1);
            }
        }

        // ---- wait for own-layer h(t-1), load own slice ----
        wait_warp(&cnt_own[t - 1], NPL, lane);
        {
            const __nv_bfloat16* srch = g_H[L] + (size_t)(t - 1) * BH;
#pragma unroll
            for (int r = 0; r < 8; ++r)
                cp16(ash_s + (hdst + r * 4 * KPAD) * 2, srch + (brow + r * 4) * 512 + kcol);
            cp_commit();
        }

        // ---- prefetch x(t+1) while h(t-1) is in flight ----
        if (t < TT) {
            if (L == 1) wait_warp(&cnt_l0[t + 1], NPL, lane);
            const __nv_bfloat16* srcx = (L == 0) ? (g_X + (size_t)t * BH)
                                                 : (g_H[0] + (size_t)(t + 1) * BH);
#pragma unroll
            for (int r = 0; r < 8; ++r)
                cp16(ash_s + (xdst + r * 4 * KPAD) * 2, srcx + (brow + r * 4) * 512 + kcol);
            cp_commit();
            cp_wait<1>();          // h group done, x(t+1) still pending
        } else {
            cp_wait<0>();
        }
        __syncwarp();

        // ---- h-half MMA ----
#pragma unroll
        for (int kc = 0; kc < 4; ++kc) {
            int k0 = 512 + ks * 64 + kc * 16 + t4 * 2;
#pragma unroll
            for (int nt = 0; nt < 4; ++nt) {
                const __nv_bfloat16* bp = Ash + (nt * 8 + gid) * KPAD + k0;
                uint32_t b0 = *(const uint32_t*)bp;
                uint32_t b1 = *(const uint32_t*)(bp + 8);
                mma16816(acc[0][nt], areg[1][kc][0], b0, b1);
                mma16816(acc[1][nt], areg[1][kc][1], b0, b1);
            }
        }

        // ---- write k-partials ----
#pragma unroll
        for (int mb = 0; mb < 2; ++mb)
#pragma unroll
            for (int nt = 0; nt < 4; ++nt) {
                int r = ks * 32 + mb * 16 + gid;
                int c = nt * 8 + t4 * 2;
                Psum[r * 33 + c]           = acc[mb][nt][0];
                Psum[r * 33 + c + 1]       = acc[mb][nt][1];
                Psum[(r + 8) * 33 + c]     = acc[mb][nt][2];
                Psum[(r + 8) * 33 + c + 1] = acc[mb][nt][3];
            }
        __syncthreads();

        // ---- reduce + cell update: thread (b = tid>>3, j = tid&7) ----
        {
            float gv[4];
#pragma unroll
            for (int g = 0; g < 4; ++g) {
                int row = g * 8 + jact;
                float v = bias_r[g];
#pragma unroll
                for (int w = 0; w < 8; ++w) v += Psum[(w * 32 + row) * 33 + bact];
                gv[g] = v;
            }
            float ig = sigmoidf_(gv[0]);
            float fg = sigmoidf_(gv[1]);
            float gg = tanhf(gv[2]);
            float og = sigmoidf_(gv[3]);
            c_reg = fg * c_reg + ig * gg;
            float h_new = og * tanhf(c_reg);
            g_H[L][(size_t)t * BH + bact * 512 + s * 8 + jact] = __float2bfloat16(h_new);
        }
        __syncthreads();   // all h stores done (also protects Psum reuse)

        // ---- publish ----
        if (tid == 0) red_rel(&cnt_own[t]);
    }
}

// ---------------- final FC + sigmoid ----------------------------------------
__global__ void fc_kernel(const float* __restrict__ fc_w,
                          const float* __restrict__ fc_b,
                          float* __restrict__ out) {
    __shared__ float part[512];
    int tid = threadIdx.x;                 // 512 threads: (b, o, p8)
    int p = tid & 7, o = (tid >> 3) & 1, b = tid >> 4;
    const __nv_bfloat16* h = g_H[1] + (size_t)TT * BH + b * 512 + p * 64;
    const float* w = fc_w + o * 512 + p * 64;
    float sum = 0.0f;
#pragma unroll
    for (int u = 0; u < 64; ++u) sum += __bfloat162float(h[u]) * w[u];
    part[tid] = sum;
    __syncthreads();
    if (p == 0) {
        float v = fc_b[o];
#pragma unroll
        for (int q = 0; q < 8; ++q) v += part[tid + q];
        out[b * 2 + o] = sigmoidf_(v);
    }
}

// ---------------- launch -----------------------------------------------------
extern "C" void kernel_launch(void* const* d_in, const int* in_sizes, int n_in,
                              void* d_out, int out_size) {
    const int*   tokens = (const int*)d_in[0];
    const float* emb    = (const float*)d_in[1];
    const float* w_ih   = (const float*)d_in[2];
    const float* w_hh   = (const float*)d_in[3];
    const float* b_ih   = (const float*)d_in[4];
    const float* b_hh   = (const float*)d_in[5];
    const float* fc_w   = (const float*)d_in[6];
    const float* fc_b   = (const float*)d_in[7];
    float* out = (float*)d_out;

    cudaFuncSetAttribute(lstm_kernel, cudaFuncAttributeMaxDynamicSharedMemorySize, SMEM_BYTES);

    prep_w_kernel<<<16384, 256>>>(w_ih, w_hh, b_ih, b_hh);
    gather_x_kernel<<<16384, 256>>>(tokens, emb);
    init_kernel<<<64, 256>>>();
    lstm_kernel<<<NCTA, 256, SMEM_BYTES>>>();
    fc_kernel<<<1, 512>>>(fc_w, fc_b, out);
}